// round 8
// baseline (speedup 1.0000x reference)
#include <cuda_runtime.h>
#include <cuda_bf16.h>
#include <cstdint>

// LSTM decoder: B=1024, H=128, O=7, T=512.
// gates = h @ (W_ih+W_hh)^T + (b_ih+b_hh)
// 128 blocks x 256 threads. K-SPLIT: thread (u = t&127, kh = t>>7) computes
// partial gate sums for ALL 8 batch rows over its 64-k half. Per-warp weight
// LDS halves vs row-split; 2 warps/SMSP (one per k-half) hide latency.
// Partials exchanged via SMEM; elementwise split 4 rows/thread; 2 syncs/step.
// Inner products in packed fp32x2 (fma.rn.f32x2).
// Gates i,f,g weights in SMEM; o-gate streamed from L2 with 4-ahead prefetch.

#define B_TOTAL   1024
#define HID       128
#define GATES     512
#define T_STEPS   512
#define OUT_DIM   7
#define ROWS      8
#define NBLOCKS   (B_TOTAL / ROWS)   // 128
#define TPB       256

__device__ float4 g_W[32 * GATES];   // [k4][g] combined transposed weights, 256 KB
__device__ float  g_bias[GATES];

// ---------- helpers ----------
__device__ __forceinline__ void ffma2(unsigned long long& d,
                                      unsigned long long a,
                                      unsigned long long b) {
    asm("fma.rn.f32x2 %0, %1, %2, %0;" : "+l"(d) : "l"(a), "l"(b));
}
__device__ __forceinline__ unsigned long long pack_bias(float b) {
    unsigned long long v;
    asm("mov.b64 %0, {%1, %2};" : "=l"(v) : "f"(b), "f"(0.0f));
    return v;
}
__device__ __forceinline__ float pairsum(unsigned long long v) {
    float a, b;
    asm("mov.b64 {%0, %1}, %2;" : "=f"(a), "=f"(b) : "l"(v));
    return a + b;
}
__device__ __forceinline__ float sigf(float x) {
    return __fdividef(1.0f, 1.0f + __expf(-x));
}
__device__ __forceinline__ float tanh_fast(float x) {
    return __fdividef(2.0f, 1.0f + __expf(-2.0f * x)) - 1.0f;
}

// ---------- prep ----------
__global__ void prep_kernel(const float* __restrict__ Wih,
                            const float* __restrict__ Whh,
                            const float* __restrict__ bih,
                            const float* __restrict__ bhh) {
    int idx = blockIdx.x * blockDim.x + threadIdx.x;
    if (idx < 32 * GATES) {
        int g  = idx & (GATES - 1);
        int k4 = idx >> 9;
        int base = g * HID + k4 * 4;
        float4 v;
        v.x = Wih[base + 0] + Whh[base + 0];
        v.y = Wih[base + 1] + Whh[base + 1];
        v.z = Wih[base + 2] + Whh[base + 2];
        v.w = Wih[base + 3] + Whh[base + 3];
        g_W[k4 * GATES + g] = v;
    }
    if (idx < GATES) g_bias[idx] = bih[idx] + bhh[idx];
}

// ---------- SMEM layout (floats) ----------
#define SW_F4       (32 * 384)                    // 12288 float4 : gates i,f,g (192 KB)
#define SH_OFF_F    (SW_F4 * 4)                   // 49152 : h double buffer 2*8*128 (8 KB)
#define SEX_OFF_F   (SH_OFF_F + 2 * ROWS * HID)   // 51200 : float4[8][128] partials (16 KB)
#define SWOUT_OFF_F (SEX_OFF_F + ROWS * HID * 4)  // 55296 : float4[7][33]
#define SMEM_BYTES  ((SWOUT_OFF_F + OUT_DIM * 33 * 4) * 4)   // 224880

__global__ void __launch_bounds__(TPB, 1)
lstm_kernel(const float* __restrict__ ctx,
            const float* __restrict__ Wout,
            const float* __restrict__ bout,
            float* __restrict__ out) {
    extern __shared__ float smem[];
    float4* s_w    = reinterpret_cast<float4*>(smem);
    float*  s_h    = smem + SH_OFF_F;
    float4* s_ex   = reinterpret_cast<float4*>(smem + SEX_OFF_F);   // [row][u]
    float4* s_wout = reinterpret_cast<float4*>(smem + SWOUT_OFF_F);

    const int t   = threadIdx.x;
    const int u   = t & (HID - 1);     // hidden unit
    const int kh  = t >> 7;            // k-half: 0 -> k4 0..15, 1 -> k4 16..31
    const int kb  = kh * 16;           // k4 base
    const int mrb = kh * 4;            // elementwise rows mrb..mrb+3
    const int blk = blockIdx.x;

    // stage W (i,f,g) into shared
    for (int i = t; i < SW_F4; i += TPB) {
        int k4 = i / 384;
        int g  = i - k4 * 384;
        s_w[i] = g_W[k4 * GATES + g];
    }
    // stage W_out (padded pitch 33)
    const float4* Wout4 = reinterpret_cast<const float4*>(Wout);
    for (int i = t; i < OUT_DIM * 32; i += TPB) {
        int o = i / 32, kk = i - o * 32;
        s_wout[o * 33 + kk] = Wout4[o * 32 + kk];
    }
    // h0 = ctx[b][255][:]
    for (int i = t; i < ROWS * HID; i += TPB) {
        int r = i >> 7, col = i & (HID - 1);
        int b = blk * ROWS + r;
        s_h[r * HID + col] = ctx[((size_t)b * 256 + 255) * HID + col];
    }

    // biases folded into kh=0's accumulator init only (avoid double count)
    const unsigned long long bi = (kh == 0) ? pack_bias(g_bias[u])           : 0ull;
    const unsigned long long bf = (kh == 0) ? pack_bias(g_bias[HID + u])     : 0ull;
    const unsigned long long bg = (kh == 0) ? pack_bias(g_bias[2 * HID + u]) : 0ull;
    const unsigned long long bo = (kh == 0) ? pack_bias(g_bias[3 * HID + u]) : 0ull;

    // o-gate L2 stream base (this thread's k-half rows)
    const ulonglong2* __restrict__ wO =
        reinterpret_cast<const ulonglong2*>(&g_W[3 * HID + u]);

    // pred mapping: each of the 8 warps owns one batch row, 7 active lanes
    const int pr = t >> 5;             // row 0..7 (warp id)
    const int po = t & 31;             // active if < 7
    const float bpred = (po < OUT_DIM) ? bout[po] : 0.0f;
    float* out_base = out + ((size_t)(blk * ROWS + pr) * T_STEPS) * OUT_DIM + po;

    float c[4];
#pragma unroll
    for (int r = 0; r < 4; r++) c[r] = 0.0f;

    __syncthreads();

    int cur = 0;
    for (int s = 0; s < T_STEPS; s++) {
        const float* hc = s_h + cur * (ROWS * HID);
        float*       hn = s_h + (cur ^ 1) * (ROWS * HID);

        unsigned long long a0[ROWS], a1[ROWS], a2[ROWS], a3[ROWS];
#pragma unroll
        for (int r = 0; r < ROWS; r++) { a0[r] = bi; a1[r] = bf; a2[r] = bg; a3[r] = bo; }

        // o-gate prefetch pipeline: 4 rows ahead within this k-half
        ulonglong2 w3buf[4];
#pragma unroll
        for (int j = 0; j < 4; j++) w3buf[j] = __ldg(&wO[(size_t)(kb + j) * GATES]);

#pragma unroll 4
        for (int kq = 0; kq < 16; kq++) {
            const int k4 = kb + kq;
            ulonglong2 w0 = *reinterpret_cast<const ulonglong2*>(&s_w[k4 * 384 + u]);
            ulonglong2 w1 = *reinterpret_cast<const ulonglong2*>(&s_w[k4 * 384 + HID + u]);
            ulonglong2 w2 = *reinterpret_cast<const ulonglong2*>(&s_w[k4 * 384 + 2 * HID + u]);
            ulonglong2 w3 = w3buf[kq & 3];
            if ((kq & 3) == 3 && kq + 1 < 16) {
#pragma unroll
                for (int j = 0; j < 4; j++)
                    w3buf[j] = __ldg(&wO[(size_t)(k4 + 1 + j) * GATES]);
            }
#pragma unroll
            for (int r = 0; r < ROWS; r++) {
                ulonglong2 h2 = *reinterpret_cast<const ulonglong2*>(hc + r * HID + k4 * 4); // full-warp bcast
                ffma2(a0[r], h2.x, w0.x); ffma2(a0[r], h2.y, w0.y);
                ffma2(a1[r], h2.x, w1.x); ffma2(a1[r], h2.y, w1.y);
                ffma2(a2[r], h2.x, w2.x); ffma2(a2[r], h2.y, w2.y);
                ffma2(a3[r], h2.x, w3.x); ffma2(a3[r], h2.y, w3.y);
            }
        }

        // collapse accumulators to scalars
        float p0[ROWS], p1[ROWS], p2[ROWS], p3[ROWS];
#pragma unroll
        for (int r = 0; r < ROWS; r++) {
            p0[r] = pairsum(a0[r]);
            p1[r] = pairsum(a1[r]);
            p2[r] = pairsum(a2[r]);
            p3[r] = pairsum(a3[r]);
        }

        // exchange: write partials for the rows my PARTNER (u, 1-kh) owns
#pragma unroll
        for (int r = 0; r < 4; r++) {
            int wr = (1 - kh) * 4 + r;
            s_ex[wr * HID + u] = make_float4(p0[wr], p1[wr], p2[wr], p3[wr]);
        }
        __syncthreads();

        // reduce + LSTM elementwise on my 4 rows
#pragma unroll
        for (int r = 0; r < 4; r++) {
            int mr = mrb + r;
            float4 p = s_ex[mr * HID + u];
            float gi = p0[mr] + p.x;
            float gf = p1[mr] + p.y;
            float gg = p2[mr] + p.z;
            float go = p3[mr] + p.w;
            float iv = sigf(gi);
            float fv = sigf(gf);
            float gv = tanh_fast(gg);
            float ov = sigf(go);
            c[r] = fv * c[r] + iv * gv;
            hn[mr * HID + u] = ov * tanh_fast(c[r]);
        }
        __syncthreads();

        // pred = h_new @ W_out^T + b_out  (7 lanes per warp; overlaps next GEMM)
        if (po < OUT_DIM) {
            const float4* hr = reinterpret_cast<const float4*>(hn + pr * HID);
            const float4* wr = s_wout + po * 33;
            float pa = 0.0f;
#pragma unroll 8
            for (int kk = 0; kk < 32; kk++) {
                float4 hv = hr[kk];
                float4 wv = wr[kk];
                pa += hv.x * wv.x + hv.y * wv.y + hv.z * wv.z + hv.w * wv.w;
            }
            out_base[(size_t)s * OUT_DIM] = pa + bpred;
        }
        cur ^= 1;
    }
}

extern "C" void kernel_launch(void* const* d_in, const int* in_sizes, int n_in,
                              void* d_out, int out_size) {
    const float* ctx  = (const float*)d_in[0];
    const float* Wih  = (const float*)d_in[1];
    const float* Whh  = (const float*)d_in[2];
    const float* bih  = (const float*)d_in[3];
    const float* bhh  = (const float*)d_in[4];
    const float* Wout = (const float*)d_in[5];
    const float* bout = (const float*)d_in[6];
    float* out = (float*)d_out;

    cudaFuncSetAttribute(lstm_kernel, cudaFuncAttributeMaxDynamicSharedMemorySize, SMEM_BYTES);

    prep_kernel<<<64, 256>>>(Wih, Whh, bih, bhh);
    lstm_kernel<<<NBLOCKS, TPB, SMEM_BYTES>>>(ctx, Wout, bout, out);
}

// round 9
// speedup vs baseline: 1.2132x; 1.2132x over previous
#include <cuda_runtime.h>
#include <cuda_bf16.h>
#include <cstdint>

// LSTM decoder: B=1024, H=128, O=7, T=512.
// gates = h @ (W_ih+W_hh)^T + (b_ih+b_hh)
// 128 blocks x 128 threads (R3 base). Thread t owns unit u=t, all 4 gates,
// all 8 rows. REUSE-ORDERED FMA: groups of 8 consecutive fma.rn.f32x2 sharing
// the same weight operand (src2 reuse-cache hit -> target rt 2/SMSP).
// Double-buffered per-k4 operand prefetch (h-pairs + smem weights 1 ahead,
// o-gate LDG 2 ahead). One sync per step.

#define B_TOTAL   1024
#define HID       128
#define GATES     512
#define T_STEPS   512
#define OUT_DIM   7
#define ROWS      8
#define NBLOCKS   (B_TOTAL / ROWS)   // 128
#define TPB       128

__device__ float4 g_W[32 * GATES];   // [k4][g] combined transposed weights, 256 KB
__device__ float  g_bias[GATES];

// ---------- helpers ----------
__device__ __forceinline__ void ffma2(unsigned long long& d,
                                      unsigned long long a,
                                      unsigned long long b) {
    asm("fma.rn.f32x2 %0, %1, %2, %0;" : "+l"(d) : "l"(a), "l"(b));
}
__device__ __forceinline__ unsigned long long pack_bias(float b) {
    unsigned long long v;
    asm("mov.b64 %0, {%1, %2};" : "=l"(v) : "f"(b), "f"(0.0f));
    return v;
}
__device__ __forceinline__ float pairsum(unsigned long long v) {
    float a, b;
    asm("mov.b64 {%0, %1}, %2;" : "=f"(a), "=f"(b) : "l"(v));
    return a + b;
}
__device__ __forceinline__ float sigf(float x) {
    return __fdividef(1.0f, 1.0f + __expf(-x));
}
__device__ __forceinline__ float tanh_fast(float x) {
    return __fdividef(2.0f, 1.0f + __expf(-2.0f * x)) - 1.0f;
}

// ---------- prep ----------
__global__ void prep_kernel(const float* __restrict__ Wih,
                            const float* __restrict__ Whh,
                            const float* __restrict__ bih,
                            const float* __restrict__ bhh) {
    int idx = blockIdx.x * blockDim.x + threadIdx.x;
    if (idx < 32 * GATES) {
        int g  = idx & (GATES - 1);
        int k4 = idx >> 9;
        int base = g * HID + k4 * 4;
        float4 v;
        v.x = Wih[base + 0] + Whh[base + 0];
        v.y = Wih[base + 1] + Whh[base + 1];
        v.z = Wih[base + 2] + Whh[base + 2];
        v.w = Wih[base + 3] + Whh[base + 3];
        g_W[k4 * GATES + g] = v;
    }
    if (idx < GATES) g_bias[idx] = bih[idx] + bhh[idx];
}

// ---------- SMEM layout (floats) ----------
#define SW_F4       (32 * 384)                    // 12288 float4 : gates i,f,g (192 KB)
#define SH_OFF_F    (SW_F4 * 4)                   // 49152 : h double buffer 2*8*128 (8 KB)
#define SWOUT_OFF_F (SH_OFF_F + 2 * ROWS * HID)   // 51200 : float4[7][33]
#define SMEM_BYTES  ((SWOUT_OFF_F + OUT_DIM * 33 * 4) * 4)   // 208496

__global__ void __launch_bounds__(TPB, 1)
lstm_kernel(const float* __restrict__ ctx,
            const float* __restrict__ Wout,
            const float* __restrict__ bout,
            float* __restrict__ out) {
    extern __shared__ float smem[];
    float4* s_w    = reinterpret_cast<float4*>(smem);
    float*  s_h    = smem + SH_OFF_F;
    float4* s_wout = reinterpret_cast<float4*>(smem + SWOUT_OFF_F);

    const int t   = threadIdx.x;   // hidden unit
    const int blk = blockIdx.x;

    // stage W (i,f,g) into shared
    for (int i = t; i < SW_F4; i += TPB) {
        int k4 = i / 384;
        int g  = i - k4 * 384;
        s_w[i] = g_W[k4 * GATES + g];
    }
    // stage W_out (padded pitch 33)
    const float4* Wout4 = reinterpret_cast<const float4*>(Wout);
    for (int i = t; i < OUT_DIM * 32; i += TPB) {
        int o = i / 32, kk = i - o * 32;
        s_wout[o * 33 + kk] = Wout4[o * 32 + kk];
    }
    // h0 = ctx[b][255][:]
    for (int r = 0; r < ROWS; r++) {
        int b = blk * ROWS + r;
        s_h[r * HID + t] = ctx[((size_t)b * 256 + 255) * HID + t];
    }

    // biases of unit t's 4 gates, packed for accumulator init
    const unsigned long long bi = pack_bias(g_bias[t]);
    const unsigned long long bf = pack_bias(g_bias[HID + t]);
    const unsigned long long bg = pack_bias(g_bias[2 * HID + t]);
    const unsigned long long bo = pack_bias(g_bias[3 * HID + t]);

    // o-gate L2 stream base (row pitch GATES ulonglong2 per k4)
    const ulonglong2* __restrict__ wO =
        reinterpret_cast<const ulonglong2*>(&g_W[3 * HID + t]);

    // pred mapping: 56 threads spread over all warps
    const int pr = t >> 4;          // row 0..7
    const int po = t & 15;          // out idx, active if < 7
    const float bpred = (po < OUT_DIM) ? bout[po] : 0.0f;
    float* out_base = out + ((size_t)(blk * ROWS + pr) * T_STEPS) * OUT_DIM + po;

    float c[ROWS];
#pragma unroll
    for (int r = 0; r < ROWS; r++) c[r] = 0.0f;

    __syncthreads();

    int cur = 0;
    for (int s = 0; s < T_STEPS; s++) {
        const float* hc = s_h + cur * (ROWS * HID);
        float*       hn = s_h + (cur ^ 1) * (ROWS * HID);

        unsigned long long a0[ROWS], a1[ROWS], a2[ROWS], a3[ROWS];
#pragma unroll
        for (int r = 0; r < ROWS; r++) { a0[r] = bi; a1[r] = bf; a2[r] = bg; a3[r] = bo; }

        // double-buffered operands
        ulonglong2 hb[2][ROWS];     // h pairs for one k4, 8 rows
        ulonglong2 wb[2][3];        // w0,w1,w2 (smem)
        ulonglong2 w3b[2];          // o-gate (gmem, distance-2 prefetch)

        // prologue: k4=0 operands + o-gate k4=0,1
#pragma unroll
        for (int r = 0; r < ROWS; r++)
            hb[0][r] = *reinterpret_cast<const ulonglong2*>(hc + r * HID);
        wb[0][0] = *reinterpret_cast<const ulonglong2*>(&s_w[t]);
        wb[0][1] = *reinterpret_cast<const ulonglong2*>(&s_w[HID + t]);
        wb[0][2] = *reinterpret_cast<const ulonglong2*>(&s_w[2 * HID + t]);
        w3b[0] = __ldg(&wO[0]);
        w3b[1] = __ldg(&wO[(size_t)GATES]);

        // one k4 iteration: compute on buffer CB, load k4+1 into CB^1
#define K4_STEP(k4, CB)                                                          \
        {                                                                        \
            if ((k4) < 31) {                                                     \
                const int nk = (k4) + 1;                                         \
                wb[CB ^ 1][0] = *reinterpret_cast<const ulonglong2*>(&s_w[nk * 384 + t]);            \
                wb[CB ^ 1][1] = *reinterpret_cast<const ulonglong2*>(&s_w[nk * 384 + HID + t]);      \
                wb[CB ^ 1][2] = *reinterpret_cast<const ulonglong2*>(&s_w[nk * 384 + 2 * HID + t]);  \
                _Pragma("unroll")                                                \
                for (int r = 0; r < ROWS; r++)                                   \
                    hb[CB ^ 1][r] = *reinterpret_cast<const ulonglong2*>(hc + r * HID + nk * 4);     \
            }                                                                    \
            ulonglong2 w3 = w3b[(k4) & 1];                                       \
            if ((k4) + 2 < 32)                                                   \
                w3b[(k4) & 1] = __ldg(&wO[(size_t)((k4) + 2) * GATES]);          \
            /* reuse-ordered FMA: 8 consecutive FFMA2 share the same w operand */ \
            _Pragma("unroll")                                                    \
            for (int r = 0; r < ROWS; r++) ffma2(a0[r], hb[CB][r].x, wb[CB][0].x); \
            _Pragma("unroll")                                                    \
            for (int r = 0; r < ROWS; r++) ffma2(a0[r], hb[CB][r].y, wb[CB][0].y); \
            _Pragma("unroll")                                                    \
            for (int r = 0; r < ROWS; r++) ffma2(a1[r], hb[CB][r].x, wb[CB][1].x); \
            _Pragma("unroll")                                                    \
            for (int r = 0; r < ROWS; r++) ffma2(a1[r], hb[CB][r].y, wb[CB][1].y); \
            _Pragma("unroll")                                                    \
            for (int r = 0; r < ROWS; r++) ffma2(a2[r], hb[CB][r].x, wb[CB][2].x); \
            _Pragma("unroll")                                                    \
            for (int r = 0; r < ROWS; r++) ffma2(a2[r], hb[CB][r].y, wb[CB][2].y); \
            _Pragma("unroll")                                                    \
            for (int r = 0; r < ROWS; r++) ffma2(a3[r], hb[CB][r].x, w3.x);        \
            _Pragma("unroll")                                                    \
            for (int r = 0; r < ROWS; r++) ffma2(a3[r], hb[CB][r].y, w3.y);        \
        }

        for (int k4g = 0; k4g < 16; k4g++) {
            K4_STEP(2 * k4g,     0)
            K4_STEP(2 * k4g + 1, 1)
        }
#undef K4_STEP

        // LSTM elementwise — fully thread-local (8 rows)
#pragma unroll
        for (int r = 0; r < ROWS; r++) {
            float gi = pairsum(a0[r]);
            float gf = pairsum(a1[r]);
            float gg = pairsum(a2[r]);
            float go = pairsum(a3[r]);
            float iv = sigf(gi);
            float fv = sigf(gf);
            float gv = tanh_fast(gg);
            float ov = sigf(go);
            c[r] = fv * c[r] + iv * gv;
            hn[r * HID + t] = ov * tanh_fast(c[r]);
        }
        __syncthreads();

        // pred = h_new @ W_out^T + b_out  (56 threads; overlaps next GEMM)
        if (po < OUT_DIM) {
            const float4* hr = reinterpret_cast<const float4*>(hn + pr * HID);
            const float4* wr = s_wout + po * 33;
            float pa = 0.0f;
#pragma unroll 8
            for (int kk = 0; kk < 32; kk++) {
                float4 hv = hr[kk];
                float4 wv = wr[kk];
                pa += hv.x * wv.x + hv.y * wv.y + hv.z * wv.z + hv.w * wv.w;
            }
            out_base[(size_t)s * OUT_DIM] = pa + bpred;
        }
        cur ^= 1;
    }
}

extern "C" void kernel_launch(void* const* d_in, const int* in_sizes, int n_in,
                              void* d_out, int out_size) {
    const float* ctx  = (const float*)d_in[0];
    const float* Wih  = (const float*)d_in[1];
    const float* Whh  = (const float*)d_in[2];
    const float* bih  = (const float*)d_in[3];
    const float* bhh  = (const float*)d_in[4];
    const float* Wout = (const float*)d_in[5];
    const float* bout = (const float*)d_in[6];
    float* out = (float*)d_out;

    cudaFuncSetAttribute(lstm_kernel, cudaFuncAttributeMaxDynamicSharedMemorySize, SMEM_BYTES);

    prep_kernel<<<64, 256>>>(Wih, Whh, bih, bhh);
    lstm_kernel<<<NBLOCKS, TPB, SMEM_BYTES>>>(ctx, Wout, bout, out);
}